// round 10
// baseline (speedup 1.0000x reference)
#include <cuda_runtime.h>
#include <cstdint>

// ---------------------------------------------------------------------------
// NoteAxis: 2-layer LSTM, B=4096, U=128, 128 steps, teacher-forced.
// Persistent fp32 kernel, fma.rn.f32x2 packing a unit pair per register.
// R9: weights are NOT staged through SMEM. They live in a per-thread-
// contiguous permuted layout in global memory (L2-resident, 1MB) and are
// read with 2x LDG.128 per k per thread, plain C++ loads so ptxas schedules
// them. This removes cp.async and all 32 per-chunk barriers (5 barriers/step
// remain), letting LSU/LDG/FMA from different warps overlap instead of
// phase-alternating in lockstep.
// 128 CTAs x 256 threads; CTA owns 32 batch rows for all 128 steps.
// Thread tile: 2 units x 4 gates x 8 batch rows; cell state in registers.
// ---------------------------------------------------------------------------

#define B_TOTAL   4096
#define NSTEP     128
#define FDIM      127
#define UNITS     128
#define GATES     512
#define KDIM      256
#define BT        32
#define NCTA      (B_TOTAL / BT)       // 128
#define NTHREAD   256

// x region: rows 0..127 = x_t, 128..255 = h0, 256..383 = h1.
// Each row: 32 batch values DUPLICATED ((v,v) pairs) in 4 bank-swizzled
// slices of 8: slice s=b>>3 at byte offset s*64 + (s>>1)*16.
#define XROWF     68                   // floats per row (272 B, 16B-aligned)
#define XROWU     34                   // ull per row
#define NXROW     384

#define OFF_WO    (NXROW * XROWF)      // 26112
#define OFF_BO    (OFF_WO + UNITS)
#define SMEM_FLOATS (OFF_BO + 4)
#define SMEM_BYTES  (SMEM_FLOATS * 4)  // ~104.5 KB

// ---------------- persistent device scratch (no runtime alloc) -------------
// Permuted weights: ull (=float2 over unit pair) index = k*256 + wgrp*4 + g.
// Thread (wgrp) reads 32 contiguous bytes per k -> 2x LDG.128.
__device__ unsigned long long g_W0p[KDIM * GATES / 2];
__device__ unsigned long long g_W1p[KDIM * GATES / 2];
__device__ unsigned long long g_b0p[GATES / 2];   // index wgrp*4+g, (b,b+1)
__device__ unsigned long long g_b1p[GATES / 2];
__device__ float g_wout[UNITS];
__device__ float g_bout[1];

__device__ __forceinline__ unsigned long long pack2(float lo, float hi) {
    unsigned long long v;
    asm("mov.b64 %0, {%1, %2};" : "=l"(v) : "f"(lo), "f"(hi));
    return v;
}
__device__ __forceinline__ void unpack2(unsigned long long v, float& lo, float& hi) {
    asm("mov.b64 {%0, %1}, %2;" : "=f"(lo), "=f"(hi) : "l"(v));
}

// ---------------------------------------------------------------------------
__global__ void noteaxis_prep(const float* __restrict__ wih0, const float* __restrict__ whh0,
                              const float* __restrict__ bih0, const float* __restrict__ bhh0,
                              const float* __restrict__ wih1, const float* __restrict__ whh1,
                              const float* __restrict__ bih1, const float* __restrict__ bhh1,
                              const float* __restrict__ wout, const float* __restrict__ bout)
{
    int idx = blockIdx.x * blockDim.x + threadIdx.x;   // over 65536 ulls
    if (idx < KDIM * GATES / 2) {
        int k  = idx >> 8;        // 0..255
        int r  = idx & 255;       // wgrp*4 + g
        int wg = r >> 2;
        int g  = r & 3;
        int c0 = g * UNITS + 2 * wg;     // column (gate-major) of unit 2*wg
        int c1 = c0 + 1;
        float a0, a1, b0, b1;
        if (k < UNITS) {
            a0 = wih0[c0 * UNITS + k]; a1 = wih0[c1 * UNITS + k];
            b0 = wih1[c0 * UNITS + k]; b1 = wih1[c1 * UNITS + k];
        } else {
            a0 = whh0[c0 * UNITS + (k - UNITS)]; a1 = whh0[c1 * UNITS + (k - UNITS)];
            b0 = whh1[c0 * UNITS + (k - UNITS)]; b1 = whh1[c1 * UNITS + (k - UNITS)];
        }
        g_W0p[idx] = pack2(a0, a1);
        g_W1p[idx] = pack2(b0, b1);
    }
    if (idx < GATES / 2) {
        int wg = idx >> 2;
        int g  = idx & 3;
        int c0 = g * UNITS + 2 * wg;
        g_b0p[idx] = pack2(bih0[c0] + bhh0[c0], bih0[c0 + 1] + bhh0[c0 + 1]);
        g_b1p[idx] = pack2(bih1[c0] + bhh1[c0], bih1[c0 + 1] + bhh1[c0 + 1]);
    }
    if (idx < UNITS) g_wout[idx] = wout[idx];
    if (idx == 0)    g_bout[0]   = bout[0];
}

// ---------------------------------------------------------------------------
__device__ __forceinline__ float ftanh_(float x) {
    float r;
    asm("tanh.approx.f32 %0, %1;" : "=f"(r) : "f"(x));
    return r;
}
__device__ __forceinline__ float fsig(float x) {
    return fmaf(0.5f, ftanh_(0.5f * x), 0.5f);
}

// byte offset of (dup'd) batch element b within an x row
__device__ __forceinline__ uint32_t bslice(int b) {
    int s = b >> 3;
    return (uint32_t)(s * 64 + (s >> 1) * 16 + (b & 7) * 8);
}

// GEMM over K=256: acc[r][g] += x[k][pair r] * w[k][unit pair, gate g].
// x from SMEM (plain loads -> LDS.128 pairs), w straight from L2 (LDG.128).
// No barriers inside; ptxas schedules/hoists freely.
__device__ __forceinline__ void gemm256(const unsigned long long* __restrict__ sxu,
                                        int xbase,                       // ull index of k=0 row + slice
                                        const ulonglong2* __restrict__ w, // + wgrp*2 already
                                        unsigned long long (&acc)[8][4])
{
#pragma unroll 4
    for (int k = 0; k < KDIM; ++k) {
        ulonglong2 wA = w[0];          // gates i, f   (f32x2 over unit pair)
        ulonglong2 wB = w[1];          // gates g, o
        w += 128;                      // next k (128 ull2 per k)
        const unsigned long long* xr = sxu + xbase;
        xbase += XROWU;
#pragma unroll
        for (int r = 0; r < 8; ++r) {
            unsigned long long xv = xr[r];
            asm("fma.rn.f32x2 %0, %1, %2, %0;" : "+l"(acc[r][0]) : "l"(xv), "l"(wA.x));
            asm("fma.rn.f32x2 %0, %1, %2, %0;" : "+l"(acc[r][1]) : "l"(xv), "l"(wA.y));
            asm("fma.rn.f32x2 %0, %1, %2, %0;" : "+l"(acc[r][2]) : "l"(xv), "l"(wB.x));
            asm("fma.rn.f32x2 %0, %1, %2, %0;" : "+l"(acc[r][3]) : "l"(xv), "l"(wB.y));
        }
    }
}

// Gates -> nonlinearity -> cell update -> dup'd h stores (plain stores).
__device__ __forceinline__ void lstm_pointwise(unsigned long long (&acc)[8][4],
                                               float (&cs)[8][2],
                                               float* hrow0, float* hrow1)
{
#pragma unroll
    for (int r = 0; r < 8; ++r) {
        float i0, i1, f0, f1, g0, g1, o0, o1;
        unpack2(acc[r][0], i0, i1);
        unpack2(acc[r][1], f0, f1);
        unpack2(acc[r][2], g0, g1);
        unpack2(acc[r][3], o0, o1);
        float c0 = fsig(f0) * cs[r][0] + fsig(i0) * ftanh_(g0);
        float c1 = fsig(f1) * cs[r][1] + fsig(i1) * ftanh_(g1);
        cs[r][0] = c0;
        cs[r][1] = c1;
        float h0 = fsig(o0) * ftanh_(c0);
        float h1 = fsig(o1) * ftanh_(c1);
        reinterpret_cast<float2*>(hrow0)[r] = make_float2(h0, h0);
        reinterpret_cast<float2*>(hrow1)[r] = make_float2(h1, h1);
    }
}

// ---------------------------------------------------------------------------
__global__ void __launch_bounds__(NTHREAD, 1)
noteaxis_lstm(const float* __restrict__ nf, const float* __restrict__ tg,
              float* __restrict__ out)
{
    extern __shared__ float smem[];
    const int tid  = threadIdx.x;
    const int wgrp = tid >> 2;   // 0..63 : unit pair {2*wgrp, 2*wgrp+1}
    const int bgrp = tid & 3;    // 0..3  : batch rows 8*bgrp..8*bgrp+7
    const int b0   = blockIdx.x * BT;

    const unsigned long long* sxu = reinterpret_cast<const unsigned long long*>(smem);

    // Zero x/h region; stage wout/bout.
    for (int i = tid; i < OFF_WO; i += NTHREAD) smem[i] = 0.0f;
    if (tid < UNITS) smem[OFF_WO + tid] = g_wout[tid];
    if (tid == 0)    smem[OFF_BO] = g_bout[0];

    float cs0[8][2], cs1[8][2];
#pragma unroll
    for (int r = 0; r < 8; ++r) {
        cs0[r][0] = 0.0f; cs0[r][1] = 0.0f;
        cs1[r][0] = 0.0f; cs1[r][1] = 0.0f;
    }

    const int xoffU = (int)(bslice(8 * bgrp) >> 3);          // ull offset in row
    const int xoffF = (int)(bslice(8 * bgrp) >> 2);          // float offset
    float* h0row0 = smem + (128 + 2 * wgrp) * XROWF + xoffF; // unit 2w
    float* h0row1 = h0row0 + XROWF;                          // unit 2w+1
    float* h1row0 = smem + (256 + 2 * wgrp) * XROWF + xoffF;
    float* h1row1 = h1row0 + XROWF;

    const ulonglong2* w0 = reinterpret_cast<const ulonglong2*>(g_W0p) + wgrp * 2;
    const ulonglong2* w1 = reinterpret_cast<const ulonglong2*>(g_W1p) + wgrp * 2;
    const ulonglong2* b0p = reinterpret_cast<const ulonglong2*>(g_b0p) + wgrp * 2;
    const ulonglong2* b1p = reinterpret_cast<const ulonglong2*>(g_b1p) + wgrp * 2;

    __syncthreads();

    for (int t = 0; t < NSTEP; ++t) {
        // ---- stage x_t (dup'd) into rows 0..127 ---------------------------
#pragma unroll
        for (int i = 0; i < 16; ++i) {
            int idx = tid + i * NTHREAD;     // 0..4095
            int b = idx >> 7;
            int f = idx & 127;
            float v;
            if (f < FDIM)
                v = nf[((b0 + b) * NSTEP + t) * FDIM + f];
            else
                v = (t > 0) ? tg[(b0 + b) * NSTEP + (t - 1)] : 0.0f;
            *reinterpret_cast<float2*>(smem + f * XROWF + (bslice(b) >> 2)) =
                make_float2(v, v);
        }
        __syncthreads();   // A: x staged

        unsigned long long acc[8][4];

        // ================= layer 0 : gates = [x|h0] @ W0 + b0 ==============
        {
            ulonglong2 bA = b0p[0], bB = b0p[1];
#pragma unroll
            for (int r = 0; r < 8; ++r) {
                acc[r][0] = bA.x; acc[r][1] = bA.y;
                acc[r][2] = bB.x; acc[r][3] = bB.y;
            }
        }
        gemm256(sxu, xoffU, w0, acc);                 // reads rows 0..255
        __syncthreads();   // B: everyone done reading h0(prev)
        lstm_pointwise(acc, cs0, h0row0, h0row1);     // writes rows 128..255
        __syncthreads();   // C: h0 visible

        // ================= layer 1 : gates = [h0|h1] @ W1 + b1 =============
        {
            ulonglong2 bA = b1p[0], bB = b1p[1];
#pragma unroll
            for (int r = 0; r < 8; ++r) {
                acc[r][0] = bA.x; acc[r][1] = bA.y;
                acc[r][2] = bB.x; acc[r][3] = bB.y;
            }
        }
        gemm256(sxu, 128 * XROWU + xoffU, w1, acc);   // reads rows 128..383
        __syncthreads();   // D: everyone done reading h1(prev)
        lstm_pointwise(acc, cs1, h1row0, h1row1);     // writes rows 256..383
        __syncthreads();   // E: h1 visible

        // ---------------- output: sigmoid(h1 . wout + bout) ---------------
        {
            int rowb = tid >> 3;
            int l8   = tid & 7;
            int so   = (int)(bslice(rowb) >> 2);
            float s = 0.0f;
#pragma unroll
            for (int jj = 0; jj < 16; ++jj) {
                int u = l8 + 8 * jj;
                s += smem[(256 + u) * XROWF + so] * smem[OFF_WO + u];
            }
            s += __shfl_xor_sync(0xffffffffu, s, 1);
            s += __shfl_xor_sync(0xffffffffu, s, 2);
            s += __shfl_xor_sync(0xffffffffu, s, 4);
            if (l8 == 0)
                out[(b0 + rowb) * NSTEP + t] = fsig(s + smem[OFF_BO]);
        }
        // Next-step x staging writes rows 0..127 only; epilogue reads rows
        // 256..383 — disjoint, and barrier A orders staging before the gemm.
    }
}

// ---------------------------------------------------------------------------
extern "C" void kernel_launch(void* const* d_in, const int* in_sizes, int n_in,
                              void* d_out, int out_size)
{
    const float* nf   = (const float*)d_in[0];
    const float* tg   = (const float*)d_in[1];
    const float* wih0 = (const float*)d_in[2];
    const float* whh0 = (const float*)d_in[3];
    const float* bih0 = (const float*)d_in[4];
    const float* bhh0 = (const float*)d_in[5];
    const float* wih1 = (const float*)d_in[6];
    const float* whh1 = (const float*)d_in[7];
    const float* bih1 = (const float*)d_in[8];
    const float* bhh1 = (const float*)d_in[9];
    const float* wout = (const float*)d_in[10];
    const float* bout = (const float*)d_in[11];
    float* out = (float*)d_out;

    cudaFuncSetAttribute(noteaxis_lstm, cudaFuncAttributeMaxDynamicSharedMemorySize, SMEM_BYTES);

    noteaxis_prep<<<(KDIM * GATES / 2 + 255) / 256, 256>>>(wih0, whh0, bih0, bhh0,
                                                           wih1, whh1, bih1, bhh1,
                                                           wout, bout);
    noteaxis_lstm<<<NCTA, NTHREAD, SMEM_BYTES>>>(nf, tg, out);
}